// round 13
// baseline (speedup 1.0000x reference)
#include <cuda_runtime.h>
#include <cuda_fp16.h>
#include <cstdint>

// AttentionOutput: causal complex leaky-relu attention + linear head.
// B=4, N=4096, F=64.  fp16 mma.sync.m16n8k16, 512 threads (16 warps), pair-balanced.

#define NT 512
#define S2 36            // half2 stride per 64-element row
// half2-unit offsets in dynamic smem
#define QR2 0
#define QI2 2304
#define KR2 4608
#define KI2 6912
#define VR2 9216         // V transposed [f][jpair], jp XOR-swizzled
#define VI2 11520
#define WR2 13824
#define WI2 16128
#define SMH2 18432
#define SMB (SMH2 * 4)   // 73728 bytes
// float-unit aliases for the linear head (Q/K/V dead by then)
#define OFR 0
#define OFI 4352
#define WATTF 8704
#define BIASF 13056

__device__ __forceinline__ uint32_t pkh2(float lo, float hi) {
    __half2 h = __floats2half2_rn(lo, hi);
    return *(uint32_t*)&h;
}
__device__ __forceinline__ float rna(float x) {
    uint32_t u;
    asm("cvt.rna.tf32.f32 %0, %1;" : "=r"(u) : "f"(x));
    return __uint_as_float(u);
}

__device__ __forceinline__ void mma16(float* c, uint32_t a0, uint32_t a1,
                                      uint32_t a2, uint32_t a3,
                                      uint32_t b0, uint32_t b1) {
    asm volatile("mma.sync.aligned.m16n8k16.row.col.f32.f16.f16.f32 "
                 "{%0,%1,%2,%3},{%4,%5,%6,%7},{%8,%9},{%0,%1,%2,%3};"
                 : "+f"(c[0]), "+f"(c[1]), "+f"(c[2]), "+f"(c[3])
                 : "r"(a0), "r"(a1), "r"(a2), "r"(a3), "r"(b0), "r"(b1));
}
__device__ __forceinline__ void mma8(float* c, float a0, float a1, float a2, float a3,
                                     float b0, float b1) {
    uint32_t A0 = __float_as_uint(a0), A1 = __float_as_uint(a1);
    uint32_t A2 = __float_as_uint(a2), A3 = __float_as_uint(a3);
    uint32_t B0 = __float_as_uint(b0), B1 = __float_as_uint(b1);
    asm volatile("mma.sync.aligned.m16n8k8.row.col.f32.tf32.tf32.f32 "
                 "{%0,%1,%2,%3},{%4,%5,%6,%7},{%8,%9},{%0,%1,%2,%3};"
                 : "+f"(c[0]), "+f"(c[1]), "+f"(c[2]), "+f"(c[3])
                 : "r"(A0), "r"(A1), "r"(A2), "r"(A3), "r"(B0), "r"(B1));
}

#define SPLIT4(x0, x1, x2, x3, h0, h1, h2, h3, l0, l1, l2, l3)              \
    float h0 = rna(x0), h1 = rna(x1), h2 = rna(x2), h3 = rna(x3);           \
    float l0 = x0 - h0, l1 = x1 - h1, l2 = x2 - h2, l3 = x3 - h3;

__global__ __launch_bounds__(NT, 1)
void attn_k(const float2* __restrict__ Qg, const float2* __restrict__ Kg,
            const float2* __restrict__ Vg, const float* __restrict__ Wg,
            const float* __restrict__ bg, float2* __restrict__ Og)
{
    extern __shared__ uint32_t smh[];
    float* smf = (float*)smh;
    const int tid = threadIdx.x, w = tid >> 5, l = tid & 31;
    const int g = l >> 2, t = l & 3;
    const int b = blockIdx.y;
    const int N = 4096;

    // 16 warps: 4x4 tiling of the 64x64 tiles, warp tile 16x16 (nb=2 n-blocks)
    const int i0w = (w >> 2) * 16, j0w = (w & 3) * 16;     // phase-1 map
    const int i0p = (w & 3) * 16, f0p = (w >> 2) * 16;     // phase-2 map
    const float scale = 1.0f / 64.0f;                      // 1/sqrt(4096)

    // complementary pair: (bx+1) + (64-bx) = 65 tile-units, all CTAs equal
    #pragma unroll 1
    for (int pi = 0; pi < 2; ++pi) {
        const int qt = pi ? (63 - (int)blockIdx.x) : (int)blockIdx.x;
        const int qi0 = qt * 64;

        __syncthreads();   // previous iteration's smem reads complete

        // ---- load Q tile (fp16-rounded, half2-packed over k) ----
        {
            const float4* Qp4 = (const float4*)(Qg + ((size_t)b * N + qi0) * 64);
            for (int idx = tid; idx < 2048; idx += NT) {
                float4 q = Qp4[idx];
                int j = idx >> 5, fp = idx & 31;
                smh[QR2 + j * S2 + fp] = pkh2(q.x, q.z);
                smh[QI2 + j * S2 + fp] = pkh2(q.y, q.w);
            }
        }

        float o_r[2][4], o_i[2][4];
        #pragma unroll
        for (int nb = 0; nb < 2; ++nb)
            #pragma unroll
            for (int r = 0; r < 4; ++r) { o_r[nb][r] = 0.f; o_i[nb][r] = 0.f; }

        for (int tt = 0; tt <= qt; ++tt) {
            const int kt = tt * 64;
            __syncthreads();   // prior phase-2 V/W reads done

            // ---- load K (rows) and V (transposed, swizzled) ----
            {
                const float4* Kp4 = (const float4*)(Kg + ((size_t)b * N + kt) * 64);
                for (int idx = tid; idx < 2048; idx += NT) {
                    float4 kv = Kp4[idx];
                    int j = idx >> 5, fp = idx & 31;
                    smh[KR2 + j * S2 + fp] = pkh2(kv.x, kv.z);
                    smh[KI2 + j * S2 + fp] = pkh2(kv.y, kv.w);
                }
                const float2* Vp = Vg + ((size_t)b * N + kt) * 64;
                for (int idx = tid; idx < 2048; idx += NT) {
                    int jp = idx >> 6, f = idx & 63;
                    float2 v0 = Vp[(2 * jp) * 64 + f];
                    float2 v1 = Vp[(2 * jp + 1) * 64 + f];
                    int js = jp ^ ((f >> 3) & 3);          // bank swizzle
                    smh[VR2 + f * S2 + js] = pkh2(v0.x, v1.x);
                    smh[VI2 + f * S2 + js] = pkh2(v0.y, v1.y);
                }
            }
            __syncthreads();

            // ---- phase 1: crr = QrKr, cii = QiKi, csi = QrKi + QiKr ----
            float crr[2][4], cii[2][4], csi[2][4];
            #pragma unroll
            for (int nb = 0; nb < 2; ++nb)
                #pragma unroll
                for (int r = 0; r < 4; ++r) { crr[nb][r] = 0.f; cii[nb][r] = 0.f; csi[nb][r] = 0.f; }

            #pragma unroll
            for (int kk = 0; kk < 4; ++kk) {
                const int k0 = kk * 8;    // half2 units (16 halves)
                const int qa = (i0w + g) * S2 + k0 + t;
                uint32_t qr0 = smh[QR2 + qa],          qr1 = smh[QR2 + qa + 8 * S2];
                uint32_t qr2 = smh[QR2 + qa + 4],      qr3 = smh[QR2 + qa + 8 * S2 + 4];
                uint32_t qi0_ = smh[QI2 + qa],         qi1 = smh[QI2 + qa + 8 * S2];
                uint32_t qi2 = smh[QI2 + qa + 4],      qi3 = smh[QI2 + qa + 8 * S2 + 4];
                #pragma unroll
                for (int nb = 0; nb < 2; ++nb) {
                    const int kb = (j0w + nb * 8 + g) * S2 + k0 + t;
                    uint32_t kr0 = smh[KR2 + kb], kr1 = smh[KR2 + kb + 4];
                    uint32_t ki0 = smh[KI2 + kb], ki1 = smh[KI2 + kb + 4];
                    mma16(crr[nb], qr0, qr1, qr2, qr3, kr0, kr1);
                    mma16(cii[nb], qi0_, qi1, qi2, qi3, ki0, ki1);
                    mma16(csi[nb], qr0, qr1, qr2, qr3, ki0, ki1);
                    mma16(csi[nb], qi0_, qi1, qi2, qi3, kr0, kr1);
                }
            }

            // ---- epilogue: scale + leaky + causal mask -> W (fp16 pairs) ----
            #pragma unroll
            for (int nb = 0; nb < 2; ++nb) {
                float vr_[4], vi_[4];
                #pragma unroll
                for (int r = 0; r < 4; ++r) {
                    int il = i0w + g + ((r & 2) ? 8 : 0);
                    int jg = kt + j0w + nb * 8 + 2 * t + (r & 1);
                    float sr = (crr[nb][r] - cii[nb][r]) * scale;
                    float si = csi[nb][r] * scale;
                    sr = sr >= 0.f ? sr : 0.01f * sr;
                    si = si >= 0.f ? si : 0.01f * si;
                    if (jg > qi0 + il) { sr = 0.f; si = 0.f; }
                    vr_[r] = sr; vi_[r] = si;
                }
                const int wb = (i0w + g) * S2 + (j0w >> 1) + nb * 4 + t;
                smh[WR2 + wb]          = pkh2(vr_[0], vr_[1]);
                smh[WR2 + wb + 8 * S2] = pkh2(vr_[2], vr_[3]);
                smh[WI2 + wb]          = pkh2(vi_[0], vi_[1]);
                smh[WI2 + wb + 8 * S2] = pkh2(vi_[2], vi_[3]);
            }
            __syncthreads();

            // ---- phase 2: O += W V ----
            #pragma unroll
            for (int kk = 0; kk < 4; ++kk) {
                const int k0 = kk * 8;
                const int wa = (i0p + g) * S2 + k0 + t;
                uint32_t wr0 = smh[WR2 + wa],          wr1 = smh[WR2 + wa + 8 * S2];
                uint32_t wr2 = smh[WR2 + wa + 4],      wr3 = smh[WR2 + wa + 8 * S2 + 4];
                uint32_t wi0 = smh[WI2 + wa],          wi1 = smh[WI2 + wa + 8 * S2];
                uint32_t wi2 = smh[WI2 + wa + 4],      wi3 = smh[WI2 + wa + 8 * S2 + 4];
                #pragma unroll
                for (int nb = 0; nb < 2; ++nb) {
                    const int f = f0p + nb * 8 + g;
                    const int xm = (f >> 3) & 3;
                    const int vb = f * S2 + k0 + (t ^ xm);
                    uint32_t v0 = smh[VR2 + vb], v1 = smh[VR2 + vb + 4];
                    uint32_t u0 = smh[VI2 + vb], u1 = smh[VI2 + vb + 4];
                    mma16(o_r[nb], wr0, wr1, wr2, wr3, v0, v1);
                    mma16(o_i[nb], wi0, wi1, wi2, wi3, u0, u1);
                }
            }
        }

        // ---- linear head via tf32 mma: out = O @ Watt^T + b ----
        __syncthreads();   // all phase-2 done; Q/K/V/W regions now dead
        #pragma unroll
        for (int nb = 0; nb < 2; ++nb)
            #pragma unroll
            for (int r = 0; r < 4; ++r) {
                int il = i0p + g + ((r & 2) ? 8 : 0);
                int fo = f0p + nb * 8 + 2 * t + (r & 1);
                smf[OFR + il * 68 + fo] = o_r[nb][r];
                smf[OFI + il * 68 + fo] = o_i[nb][r];
            }
        for (int idx = tid; idx < 64 * 64; idx += NT)
            smf[WATTF + (idx >> 6) * 68 + (idx & 63)] = Wg[idx];
        if (tid < 64) smf[BIASF + tid] = bg[tid];
        __syncthreads();

        float hr[2][4], hi_[2][4];
        #pragma unroll
        for (int nb = 0; nb < 2; ++nb)
            #pragma unroll
            for (int r = 0; r < 4; ++r) { hr[nb][r] = 0.f; hi_[nb][r] = 0.f; }

        for (int kk = 0; kk < 8; ++kk) {
            const int k0 = kk * 8;
            const int ab = OFR + (i0p + g) * 68 + k0 + t;
            float pr0 = smf[ab],     pr1 = smf[ab + 8 * 68];
            float pr2 = smf[ab + 4], pr3 = smf[ab + 8 * 68 + 4];
            const int ai = OFI + (i0p + g) * 68 + k0 + t;
            float pi0 = smf[ai],     pi1 = smf[ai + 8 * 68];
            float pi2 = smf[ai + 4], pi3 = smf[ai + 8 * 68 + 4];
            SPLIT4(pr0, pr1, pr2, pr3, orh0, orh1, orh2, orh3, orl0, orl1, orl2, orl3)
            SPLIT4(pi0, pi1, pi2, pi3, oih0, oih1, oih2, oih3, oil0, oil1, oil2, oil3)
            #pragma unroll
            for (int nb = 0; nb < 2; ++nb) {
                const int wb2 = WATTF + (f0p + nb * 8 + g) * 68 + k0 + t;
                float w0 = smf[wb2], w1 = smf[wb2 + 4];
                float wh0 = rna(w0), wl0 = w0 - wh0;
                float wh1 = rna(w1), wl1 = w1 - wh1;
                mma8(hr[nb], orh0, orh1, orh2, orh3, wh0, wh1);
                mma8(hr[nb], orl0, orl1, orl2, orl3, wh0, wh1);
                mma8(hr[nb], orh0, orh1, orh2, orh3, wl0, wl1);
                mma8(hi_[nb], oih0, oih1, oih2, oih3, wh0, wh1);
                mma8(hi_[nb], oil0, oil1, oil2, oil3, wh0, wh1);
                mma8(hi_[nb], oih0, oih1, oih2, oih3, wl0, wl1);
            }
        }

        float2* Ob = Og + ((size_t)b * N + qi0) * 64;
        #pragma unroll
        for (int nb = 0; nb < 2; ++nb)
            #pragma unroll
            for (int r = 0; r < 4; ++r) {
                int il = i0p + g + ((r & 2) ? 8 : 0);
                int fo = f0p + nb * 8 + 2 * t + (r & 1);
                float bb = smf[BIASF + fo];
                Ob[il * 64 + fo] = make_float2(hr[nb][r] + bb, hi_[nb][r] + bb);
            }
    }
}

extern "C" void kernel_launch(void* const* d_in, const int* in_sizes, int n_in,
                              void* d_out, int out_size)
{
    const float2* Q = (const float2*)d_in[0];
    const float2* K = (const float2*)d_in[1];
    const float2* V = (const float2*)d_in[2];
    const float*  W = (const float*)d_in[3];
    const float*  bb = (const float*)d_in[4];
    float2* O = (float2*)d_out;

    static bool attr_set = false;
    if (!attr_set) {
        cudaFuncSetAttribute(attn_k, cudaFuncAttributeMaxDynamicSharedMemorySize, SMB);
        attr_set = true;
    }

    attn_k<<<dim3(32, 4), NT, SMB>>>(Q, K, V, W, bb, O);
}

// round 14
// speedup vs baseline: 1.6056x; 1.6056x over previous
#include <cuda_runtime.h>
#include <cuda_fp16.h>
#include <cstdint>

// AttentionOutput: causal complex leaky-relu attention + linear head.
// B=4, N=4096, F=64.  fp16 mma.sync.m16n8k16, software-pipelined tiles,
// double-buffered K/V/W, register-staged GMEM loads. Pair-balanced CTAs.

#define NT 256
#define S2 36            // half2 stride per 64-element row
// half2-unit offsets
#define QR2 0
#define QI2 2304
#define BUF0 4608        // two K/V/W buffers of 13824 half2 each
#define BUFSZ 13824
// within a buffer: KR +0, KI +2304, VR +4608, VI +6912, WR +9216, WI +11520
#define SMH2 (4608 + 2 * 13824)
#define SMB (SMH2 * 4)   // 129024 bytes
// float-unit aliases for the linear head (Q/K regions dead by then)
#define OFR 0
#define OFI 4352
#define WATTF 8704
#define BIASF 13056

__device__ __forceinline__ uint32_t pkh2(float lo, float hi) {
    __half2 h = __floats2half2_rn(lo, hi);
    return *(uint32_t*)&h;
}
__device__ __forceinline__ float rna(float x) {
    uint32_t u;
    asm("cvt.rna.tf32.f32 %0, %1;" : "=r"(u) : "f"(x));
    return __uint_as_float(u);
}

__device__ __forceinline__ void mma16(float* c, uint32_t a0, uint32_t a1,
                                      uint32_t a2, uint32_t a3,
                                      uint32_t b0, uint32_t b1) {
    asm volatile("mma.sync.aligned.m16n8k16.row.col.f32.f16.f16.f32 "
                 "{%0,%1,%2,%3},{%4,%5,%6,%7},{%8,%9},{%0,%1,%2,%3};"
                 : "+f"(c[0]), "+f"(c[1]), "+f"(c[2]), "+f"(c[3])
                 : "r"(a0), "r"(a1), "r"(a2), "r"(a3), "r"(b0), "r"(b1));
}
__device__ __forceinline__ void mma8(float* c, float a0, float a1, float a2, float a3,
                                     float b0, float b1) {
    uint32_t A0 = __float_as_uint(a0), A1 = __float_as_uint(a1);
    uint32_t A2 = __float_as_uint(a2), A3 = __float_as_uint(a3);
    uint32_t B0 = __float_as_uint(b0), B1 = __float_as_uint(b1);
    asm volatile("mma.sync.aligned.m16n8k8.row.col.f32.tf32.tf32.f32 "
                 "{%0,%1,%2,%3},{%4,%5,%6,%7},{%8,%9},{%0,%1,%2,%3};"
                 : "+f"(c[0]), "+f"(c[1]), "+f"(c[2]), "+f"(c[3])
                 : "r"(A0), "r"(A1), "r"(A2), "r"(A3), "r"(B0), "r"(B1));
}

#define SPLIT4(x0, x1, x2, x3, h0, h1, h2, h3, l0, l1, l2, l3)              \
    float h0 = rna(x0), h1 = rna(x1), h2 = rna(x2), h3 = rna(x3);           \
    float l0 = x0 - h0, l1 = x1 - h1, l2 = x2 - h2, l3 = x3 - h3;

// phase 1 + epilogue: scores for 64x64 tile, write W into buffer `buf`
__device__ __forceinline__ void phase1_epi(uint32_t* smh, int buf, int kt, int qi0,
                                           int i0w, int j0w, int g, int t, float scale)
{
    float crr[4][4], cii[4][4], csi[4][4];
    #pragma unroll
    for (int nb = 0; nb < 4; ++nb)
        #pragma unroll
        for (int r = 0; r < 4; ++r) { crr[nb][r] = 0.f; cii[nb][r] = 0.f; csi[nb][r] = 0.f; }

    #pragma unroll
    for (int kk = 0; kk < 4; ++kk) {
        const int k0 = kk * 8;
        const int qa = (i0w + g) * S2 + k0 + t;
        uint32_t qr0 = smh[QR2 + qa],          qr1 = smh[QR2 + qa + 8 * S2];
        uint32_t qr2 = smh[QR2 + qa + 4],      qr3 = smh[QR2 + qa + 8 * S2 + 4];
        uint32_t qi0_ = smh[QI2 + qa],         qi1 = smh[QI2 + qa + 8 * S2];
        uint32_t qi2 = smh[QI2 + qa + 4],      qi3 = smh[QI2 + qa + 8 * S2 + 4];
        #pragma unroll
        for (int nb = 0; nb < 4; ++nb) {
            const int kb = buf + (j0w + nb * 8 + g) * S2 + k0 + t;
            uint32_t kr0 = smh[kb],        kr1 = smh[kb + 4];
            uint32_t ki0 = smh[kb + 2304], ki1 = smh[kb + 2304 + 4];
            mma16(crr[nb], qr0, qr1, qr2, qr3, kr0, kr1);
            mma16(cii[nb], qi0_, qi1, qi2, qi3, ki0, ki1);
            mma16(csi[nb], qr0, qr1, qr2, qr3, ki0, ki1);
            mma16(csi[nb], qi0_, qi1, qi2, qi3, kr0, kr1);
        }
    }

    #pragma unroll
    for (int nb = 0; nb < 4; ++nb) {
        float vr_[4], vi_[4];
        #pragma unroll
        for (int r = 0; r < 4; ++r) {
            int il = i0w + g + ((r & 2) ? 8 : 0);
            int jg = kt + j0w + nb * 8 + 2 * t + (r & 1);
            float sr = (crr[nb][r] - cii[nb][r]) * scale;
            float si = csi[nb][r] * scale;
            sr = sr >= 0.f ? sr : 0.01f * sr;
            si = si >= 0.f ? si : 0.01f * si;
            if (jg > qi0 + il) { sr = 0.f; si = 0.f; }
            vr_[r] = sr; vi_[r] = si;
        }
        const int wb = buf + 9216 + (i0w + g) * S2 + (j0w >> 1) + nb * 4 + t;
        smh[wb]                 = pkh2(vr_[0], vr_[1]);
        smh[wb + 8 * S2]        = pkh2(vr_[2], vr_[3]);
        smh[wb + 2304]          = pkh2(vi_[0], vi_[1]);
        smh[wb + 2304 + 8 * S2] = pkh2(vi_[2], vi_[3]);
    }
}

__device__ __forceinline__ void phase2f(uint32_t* smh, int buf, int i0p, int f0p,
                                        int g, int t, float o_r[4][4], float o_i[4][4])
{
    #pragma unroll
    for (int kk = 0; kk < 4; ++kk) {
        const int k0 = kk * 8;
        const int wa = buf + 9216 + (i0p + g) * S2 + k0 + t;
        uint32_t wr0 = smh[wa],            wr1 = smh[wa + 8 * S2];
        uint32_t wr2 = smh[wa + 4],        wr3 = smh[wa + 8 * S2 + 4];
        uint32_t wi0 = smh[wa + 2304],     wi1 = smh[wa + 2304 + 8 * S2];
        uint32_t wi2 = smh[wa + 2304 + 4], wi3 = smh[wa + 2304 + 8 * S2 + 4];
        #pragma unroll
        for (int nb = 0; nb < 4; ++nb) {
            const int f = f0p + nb * 8 + g;
            const int xm = (f >> 3) & 3;
            const int vb = buf + 4608 + f * S2 + k0 + (t ^ xm);
            uint32_t v0 = smh[vb],        v1 = smh[vb + 4];
            uint32_t u0 = smh[vb + 2304], u1 = smh[vb + 2304 + 4];
            mma16(o_r[nb], wr0, wr1, wr2, wr3, v0, v1);
            mma16(o_i[nb], wi0, wi1, wi2, wi3, u0, u1);
        }
    }
}

__global__ __launch_bounds__(NT, 1)
void attn_k(const float2* __restrict__ Qg, const float2* __restrict__ Kg,
            const float2* __restrict__ Vg, const float* __restrict__ Wg,
            const float* __restrict__ bg, float2* __restrict__ Og)
{
    extern __shared__ uint32_t smh[];
    float* smf = (float*)smh;
    const int tid = threadIdx.x, w = tid >> 5, l = tid & 31;
    const int g = l >> 2, t = l & 3;
    const int b = blockIdx.y;
    const int N = 4096;

    const int i0w = (w >> 1) * 16, j0w = (w & 1) * 32;     // phase-1 warp map
    const int i0p = (w & 3) * 16, f0p = (w >> 2) * 32;     // phase-2 warp map
    const float scale = 1.0f / 64.0f;                      // 1/sqrt(4096)

    #pragma unroll 1
    for (int pi = 0; pi < 2; ++pi) {
        const int qt = pi ? (63 - (int)blockIdx.x) : (int)blockIdx.x;
        const int qi0 = qt * 64;

        __syncthreads();   // previous iteration's smem reads complete

        // ---- prologue: load Q and KV[0] (buffer 0) ----
        {
            const float4* Qp4 = (const float4*)(Qg + ((size_t)b * N + qi0) * 64);
            const float4* Kp4 = (const float4*)(Kg + ((size_t)b * N) * 64);
            const float2* Vp  = Vg + ((size_t)b * N) * 64;
            for (int idx = tid; idx < 2048; idx += NT) {
                float4 q = Qp4[idx];
                int j = idx >> 5, fp = idx & 31;
                smh[QR2 + j * S2 + fp] = pkh2(q.x, q.z);
                smh[QI2 + j * S2 + fp] = pkh2(q.y, q.w);
                float4 kv = Kp4[idx];
                smh[BUF0 + j * S2 + fp]        = pkh2(kv.x, kv.z);
                smh[BUF0 + 2304 + j * S2 + fp] = pkh2(kv.y, kv.w);
                int jp = idx >> 6, f = idx & 63;
                float2 v0 = Vp[(2 * jp) * 64 + f];
                float2 v1 = Vp[(2 * jp + 1) * 64 + f];
                int js = jp ^ ((f >> 3) & 3);
                smh[BUF0 + 4608 + f * S2 + js] = pkh2(v0.x, v1.x);
                smh[BUF0 + 6912 + f * S2 + js] = pkh2(v0.y, v1.y);
            }
        }

        float o_r[4][4], o_i[4][4];
        #pragma unroll
        for (int nb = 0; nb < 4; ++nb)
            #pragma unroll
            for (int r = 0; r < 4; ++r) { o_r[nb][r] = 0.f; o_i[nb][r] = 0.f; }

        __syncthreads();
        phase1_epi(smh, BUF0, 0, qi0, i0w, j0w, g, t, scale);

        for (int tt = 0; tt <= qt; ++tt) {
            const int p = tt & 1;
            const int cb = BUF0 + p * BUFSZ;
            const int nbuf = BUF0 + (p ^ 1) * BUFSZ;

            __syncthreads();   // W[tt] written; KV[tt] stable; prior reads done

            // ---- interval A: stage KV[tt+1] loads, phase2(tt), then STS ----
            float4 kstg[8];
            float2 vstg0[8], vstg1[8];
            if (tt < qt) {
                const float4* Kp4 = (const float4*)(Kg + ((size_t)b * N + (tt + 1) * 64) * 64);
                const float2* Vp  = Vg + ((size_t)b * N + (tt + 1) * 64) * 64;
                #pragma unroll
                for (int u = 0; u < 8; ++u) {
                    int idx = tid + u * NT;
                    kstg[u] = Kp4[idx];
                    int jp = idx >> 6, f = idx & 63;
                    vstg0[u] = Vp[(2 * jp) * 64 + f];
                    vstg1[u] = Vp[(2 * jp + 1) * 64 + f];
                }
            }

            phase2f(smh, cb, i0p, f0p, g, t, o_r, o_i);

            if (tt < qt) {
                #pragma unroll
                for (int u = 0; u < 8; ++u) {
                    int idx = tid + u * NT;
                    int j = idx >> 5, fp = idx & 31;
                    smh[nbuf + j * S2 + fp]        = pkh2(kstg[u].x, kstg[u].z);
                    smh[nbuf + 2304 + j * S2 + fp] = pkh2(kstg[u].y, kstg[u].w);
                    int jp = idx >> 6, f = idx & 63;
                    int js = jp ^ ((f >> 3) & 3);
                    smh[nbuf + 4608 + f * S2 + js] = pkh2(vstg0[u].x, vstg1[u].x);
                    smh[nbuf + 6912 + f * S2 + js] = pkh2(vstg0[u].y, vstg1[u].y);
                }
            }

            __syncthreads();   // KV[tt+1] in smem; phase2(tt) reads done

            // ---- interval B: phase1(tt+1) + epilogue -> W[tt+1] ----
            if (tt < qt)
                phase1_epi(smh, nbuf, (tt + 1) * 64, qi0, i0w, j0w, g, t, scale);
        }

        // ---- linear head via tf32 mma: out = O @ Watt^T + b ----
        __syncthreads();
        #pragma unroll
        for (int nb = 0; nb < 4; ++nb)
            #pragma unroll
            for (int r = 0; r < 4; ++r) {
                int il = i0p + g + ((r & 2) ? 8 : 0);
                int fo = f0p + nb * 8 + 2 * t + (r & 1);
                smf[OFR + il * 68 + fo] = o_r[nb][r];
                smf[OFI + il * 68 + fo] = o_i[nb][r];
            }
        for (int idx = tid; idx < 64 * 64; idx += NT)
            smf[WATTF + (idx >> 6) * 68 + (idx & 63)] = Wg[idx];
        if (tid < 64) smf[BIASF + tid] = bg[tid];
        __syncthreads();

        float hr[4][4], hi_[4][4];
        #pragma unroll
        for (int nb = 0; nb < 4; ++nb)
            #pragma unroll
            for (int r = 0; r < 4; ++r) { hr[nb][r] = 0.f; hi_[nb][r] = 0.f; }

        for (int kk = 0; kk < 8; ++kk) {
            const int k0 = kk * 8;
            const int ab = OFR + (i0p + g) * 68 + k0 + t;
            float pr0 = smf[ab],     pr1 = smf[ab + 8 * 68];
            float pr2 = smf[ab + 4], pr3 = smf[ab + 8 * 68 + 4];
            const int ai = OFI + (i0p + g) * 68 + k0 + t;
            float pi0 = smf[ai],     pi1 = smf[ai + 8 * 68];
            float pi2 = smf[ai + 4], pi3 = smf[ai + 8 * 68 + 4];
            SPLIT4(pr0, pr1, pr2, pr3, orh0, orh1, orh2, orh3, orl0, orl1, orl2, orl3)
            SPLIT4(pi0, pi1, pi2, pi3, oih0, oih1, oih2, oih3, oil0, oil1, oil2, oil3)
            #pragma unroll
            for (int nb = 0; nb < 4; ++nb) {
                const int wb2 = WATTF + (f0p + nb * 8 + g) * 68 + k0 + t;
                float w0 = smf[wb2], w1 = smf[wb2 + 4];
                float wh0 = rna(w0), wl0 = w0 - wh0;
                float wh1 = rna(w1), wl1 = w1 - wh1;
                mma8(hr[nb], orh0, orh1, orh2, orh3, wh0, wh1);
                mma8(hr[nb], orl0, orl1, orl2, orl3, wh0, wh1);
                mma8(hr[nb], orh0, orh1, orh2, orh3, wl0, wl1);
                mma8(hi_[nb], oih0, oih1, oih2, oih3, wh0, wh1);
                mma8(hi_[nb], oil0, oil1, oil2, oil3, wh0, wh1);
                mma8(hi_[nb], oih0, oih1, oih2, oih3, wl0, wl1);
            }
        }

        float2* Ob = Og + ((size_t)b * N + qi0) * 64;
        #pragma unroll
        for (int nb = 0; nb < 4; ++nb)
            #pragma unroll
            for (int r = 0; r < 4; ++r) {
                int il = i0p + g + ((r & 2) ? 8 : 0);
                int fo = f0p + nb * 8 + 2 * t + (r & 1);
                float bb = smf[BIASF + fo];
                Ob[il * 64 + fo] = make_float2(hr[nb][r] + bb, hi_[nb][r] + bb);
            }
    }
}

extern "C" void kernel_launch(void* const* d_in, const int* in_sizes, int n_in,
                              void* d_out, int out_size)
{
    const float2* Q = (const float2*)d_in[0];
    const float2* K = (const float2*)d_in[1];
    const float2* V = (const float2*)d_in[2];
    const float*  W = (const float*)d_in[3];
    const float*  bb = (const float*)d_in[4];
    float2* O = (float2*)d_out;

    static bool attr_set = false;
    if (!attr_set) {
        cudaFuncSetAttribute(attn_k, cudaFuncAttributeMaxDynamicSharedMemorySize, SMB);
        attr_set = true;
    }

    attn_k<<<dim3(32, 4), NT, SMB>>>(Q, K, V, W, bb, O);
}